// round 14
// baseline (speedup 1.0000x reference)
#include <cuda_runtime.h>
#include <cuda_bf16.h>
#include <cuda_fp16.h>
#include <math.h>
#include <stdint.h>

// Problem constants
#define Bn   2
#define Sn   2048
#define HSn  2048
#define Hn   16
#define HKVn 4
#define Dn   128
#define Tn   (Bn*Sn)          // 4096 tokens

// -------------------- scratch (device globals; allocation-free) -----------
// fp16 planes: activations split hi/lo, weights single
__device__ __half g_xh[(size_t)Tn*HSn],       g_xl[(size_t)Tn*HSn];
__device__ __half g_wq[(size_t)Hn*Dn*HSn];
__device__ __half g_wk[(size_t)HKVn*Dn*HSn];
__device__ __half g_wv[(size_t)HKVn*Dn*HSn];
__device__ __half g_wo[(size_t)HSn*Hn*Dn];
// post-norm/rope: Q split hi/lo, K single; V single
__device__ __half g_qbh[(size_t)Tn*Hn*Dn],    g_qbl[(size_t)Tn*Hn*Dn];
__device__ __half g_kb [(size_t)Tn*HKVn*Dn];
__device__ __half g_vb [(size_t)Tn*HKVn*Dn];
// attention output hi/lo (A operand of O-projection)
__device__ __half g_aoh[(size_t)Tn*Hn*Dn],    g_aol[(size_t)Tn*Hn*Dn];

// ======================= helpers ==========================================
__device__ __forceinline__ uint32_t smem_u32(const void* p) {
    uint32_t a;
    asm("{ .reg .u64 t; cvta.to.shared.u64 t, %1; cvt.u32.u64 %0, t; }"
        : "=r"(a) : "l"(p));
    return a;
}
__device__ __forceinline__ void cpasync16(uint32_t dst, const void* src) {
    asm volatile("cp.async.cg.shared.global [%0], [%1], 16;" :: "r"(dst), "l"(src));
}
#define CP_COMMIT() asm volatile("cp.async.commit_group;" ::: "memory")
__device__ __forceinline__ void ldsm4(uint32_t* r, uint32_t addr) {
    asm volatile("ldmatrix.sync.aligned.m8n8.x4.shared.b16 {%0,%1,%2,%3}, [%4];"
        : "=r"(r[0]), "=r"(r[1]), "=r"(r[2]), "=r"(r[3]) : "r"(addr));
}
__device__ __forceinline__ void ldsm4t(uint32_t* r, uint32_t addr) {
    asm volatile("ldmatrix.sync.aligned.m8n8.x4.trans.shared.b16 {%0,%1,%2,%3}, [%4];"
        : "=r"(r[0]), "=r"(r[1]), "=r"(r[2]), "=r"(r[3]) : "r"(addr));
}
__device__ __forceinline__ void mma_f16(float* d, const uint32_t* a, const uint32_t* b) {
    asm volatile("mma.sync.aligned.m16n8k16.row.col.f32.f16.f16.f32 "
                 "{%0,%1,%2,%3}, {%4,%5,%6,%7}, {%8,%9}, {%0,%1,%2,%3};"
                 : "+f"(d[0]), "+f"(d[1]), "+f"(d[2]), "+f"(d[3])
                 : "r"(a[0]), "r"(a[1]), "r"(a[2]), "r"(a[3]),
                   "r"(b[0]), "r"(b[1]));
}
__device__ __forceinline__ uint32_t packh(__half a, __half b) {
    return (uint32_t)__half_as_ushort(a) |
           ((uint32_t)__half_as_ushort(b) << 16);
}

// ==================== fp32 -> fp16 conversions ============================
__global__ __launch_bounds__(256) void cvt_hilo_h(const float* __restrict__ x,
                                                  __half* __restrict__ h,
                                                  __half* __restrict__ l,
                                                  int n4)
{
    int i = blockIdx.x*256 + threadIdx.x;
    if (i >= n4) return;
    float4 v = ((const float4*)x)[i];
    __half h0 = __float2half_rn(v.x);
    __half h1 = __float2half_rn(v.y);
    __half h2 = __float2half_rn(v.z);
    __half h3 = __float2half_rn(v.w);
    __half l0 = __float2half_rn(v.x - __half2float(h0));
    __half l1 = __float2half_rn(v.y - __half2float(h1));
    __half l2 = __float2half_rn(v.z - __half2float(h2));
    __half l3 = __float2half_rn(v.w - __half2float(h3));
    ((ushort4*)h)[i] = make_ushort4(__half_as_ushort(h0), __half_as_ushort(h1),
                                    __half_as_ushort(h2), __half_as_ushort(h3));
    ((ushort4*)l)[i] = make_ushort4(__half_as_ushort(l0), __half_as_ushort(l1),
                                    __half_as_ushort(l2), __half_as_ushort(l3));
}

// all four weight matrices in one launch
__global__ __launch_bounds__(256) void cvt_w4(
    const float* __restrict__ w1, __half* __restrict__ d1, int n1,
    const float* __restrict__ w2, __half* __restrict__ d2, int n2,
    const float* __restrict__ w3, __half* __restrict__ d3, int n3,
    const float* __restrict__ w4, __half* __restrict__ d4, int n4)
{
    int i = blockIdx.x*256 + threadIdx.x;
    const float* s; __half* d;
    if      (i < n1)              { s = w1; d = d1; }
    else if (i < n1+n2)           { s = w2; d = d2; i -= n1; }
    else if (i < n1+n2+n3)        { s = w3; d = d3; i -= n1+n2; }
    else if (i < n1+n2+n3+n4)     { s = w4; d = d4; i -= n1+n2+n3; }
    else return;
    float4 v = ((const float4*)s)[i];
    ((ushort4*)d)[i] = make_ushort4(
        __half_as_ushort(__float2half_rn(v.x)), __half_as_ushort(__float2half_rn(v.y)),
        __half_as_ushort(__float2half_rn(v.z)), __half_as_ushort(__float2half_rn(v.w)));
}

// ========== HMMA GEMM mainloop constants ==================================
#define HARR 5120                    // fp16 per array (128 rows * 40)
#define HSTG (3*HARR*2)              // bytes per stage (Ah, Al, B) = 30720
#define HSMEM (3*HSTG)               // 92160 B

// ===== fused QKV projection + RMSNorm + RoPE + fp16 emit ==================
// grid x: 0..15 Q heads, 16..19 K heads, 20..23 V heads; grid y: 32 token tiles
__global__ __launch_bounds__(256, 1)
void gemm_qkv(const __half* __restrict__ Ah, const __half* __restrict__ Al,
              const __half* __restrict__ wq, const __half* __restrict__ wk,
              const __half* __restrict__ wv,
              const float* __restrict__ cosT, const float* __restrict__ sinT,
              const float* __restrict__ qw,  const float* __restrict__ kw,
              __half* __restrict__ qbh, __half* __restrict__ qbl,
              __half* __restrict__ kb,  __half* __restrict__ vb)
{
    extern __shared__ __half smb[];
    const uint32_t sbase = smem_u32(smb);
    const int K = HSn;

    const int bx = blockIdx.x;
    int mode, hidx;
    const __half* pB;
    if (bx < 16)      { mode = 0; hidx = bx;      pB = wq; }
    else if (bx < 20) { mode = 1; hidx = bx - 16; pB = wk; }
    else              { mode = 2; hidx = bx - 20; pB = wv; }
    const int ncol_l = hidx * 128;

    const int tid  = threadIdx.x;
    const int lane = tid & 31;
    const int wid  = tid >> 5;
    const int m0w  = (wid >> 2) * 64;
    const int n0w  = (wid & 3) * 32;
    const int mrow0 = blockIdx.y * 128;
    const int NC = K / 32;

    float acc[4][4][4];
    #pragma unroll
    for (int mt = 0; mt < 4; mt++)
        #pragma unroll
        for (int nt = 0; nt < 4; nt++)
            #pragma unroll
            for (int i = 0; i < 4; i++) acc[mt][nt][i] = 0.f;

    auto load_chunk = [&](int c, int st) {
        const int k0 = c * 32;
        const uint32_t b0 = sbase + (uint32_t)st * HSTG;
        #pragma unroll
        for (int i = 0; i < 2; i++) {
            int id  = i*256 + tid;
            int row = id >> 2;
            int cc  = id & 3;
            uint32_t d  = (uint32_t)(row*80 + cc*16);
            size_t   ga = (size_t)(mrow0 + row)*K + k0 + cc*8;
            size_t   gb = (size_t)(ncol_l + row)*K + k0 + cc*8;
            cpasync16(b0 + 0*HARR*2 + d, Ah + ga);
            cpasync16(b0 + 1*HARR*2 + d, Al + ga);
            cpasync16(b0 + 2*HARR*2 + d, pB + gb);
        }
        CP_COMMIT();
    };

    load_chunk(0, 0);
    load_chunk(1, 1);

    for (int c = 0; c < NC; c++) {
        if (c + 1 < NC) asm volatile("cp.async.wait_group 1;" ::: "memory");
        else            asm volatile("cp.async.wait_group 0;" ::: "memory");
        __syncthreads();
        if (c + 2 < NC) load_chunk(c + 2, (c + 2) % 3);

        const uint32_t b0  = sbase + (uint32_t)(c % 3) * HSTG;
        const uint32_t aHi = b0 + 0*HARR*2;
        const uint32_t aLo = b0 + 1*HARR*2;
        const uint32_t bB  = b0 + 2*HARR*2;

        #pragma unroll
        for (int ks = 0; ks < 2; ks++) {
            uint32_t ah[4][4], al[4][4], bf[2][4];
            const uint32_t aoff = (uint32_t)(ks*32 + (lane >> 4)*16);
            const uint32_t boff = (uint32_t)(ks*32 + ((lane >> 3) & 1)*16);
            #pragma unroll
            for (int mt = 0; mt < 4; mt++) {
                uint32_t r = (uint32_t)((m0w + mt*16 + (lane & 15)) * 80) + aoff;
                ldsm4(ah[mt], aHi + r);
                ldsm4(al[mt], aLo + r);
            }
            #pragma unroll
            for (int n2 = 0; n2 < 2; n2++) {
                uint32_t r = (uint32_t)((n0w + n2*16 + ((lane>>4)<<3) + (lane & 7)) * 80) + boff;
                ldsm4(bf[n2], bB + r);
            }
            #pragma unroll
            for (int mt = 0; mt < 4; mt++)
                #pragma unroll
                for (int nt = 0; nt < 4; nt++)
                    mma_f16(acc[mt][nt], ah[mt], &bf[nt>>1][(nt&1)*2]);
            #pragma unroll
            for (int mt = 0; mt < 4; mt++)
                #pragma unroll
                for (int nt = 0; nt < 4; nt++)
                    mma_f16(acc[mt][nt], al[mt], &bf[nt>>1][(nt&1)*2]);
        }
        __syncthreads();
    }

    if (mode == 2) {
        // V: direct fp16 single-plane emit
        #pragma unroll
        for (int mt = 0; mt < 4; mt++)
            #pragma unroll
            for (int nt = 0; nt < 4; nt++) {
                const float* d = acc[mt][nt];
                int row = mrow0 + m0w + mt*16 + (lane >> 2);
                int col = n0w + nt*8 + (lane & 3)*2;
                size_t o0 = ((size_t)row*HKVn + hidx)*Dn + col;
                size_t o1 = ((size_t)(row+8)*HKVn + hidx)*Dn + col;
                *(uint32_t*)(vb + o0) = packh(__float2half_rn(d[0]), __float2half_rn(d[1]));
                *(uint32_t*)(vb + o1) = packh(__float2half_rn(d[2]), __float2half_rn(d[3]));
            }
        return;
    }

    // Q/K: stage fp32 tile, then per-row RMSNorm + RoPE
    float* sm32 = (float*)smb;      // 128 rows x stride 129 = 66048 B
    #pragma unroll
    for (int mt = 0; mt < 4; mt++)
        #pragma unroll
        for (int nt = 0; nt < 4; nt++) {
            const float* d = acc[mt][nt];
            int row = m0w + mt*16 + (lane >> 2);
            int col = n0w + nt*8 + (lane & 3)*2;
            sm32[(row  )*129 + col] = d[0]; sm32[(row  )*129 + col+1] = d[1];
            sm32[(row+8)*129 + col] = d[2]; sm32[(row+8)*129 + col+1] = d[3];
        }
    __syncthreads();

    const float* w = (mode == 0) ? qw : kw;
    const int row = tid >> 1;
    const int half = tid & 1;
    const float* rp = sm32 + row*129;

    float ss = 0.f;
    #pragma unroll 16
    for (int j = 0; j < 64; j++) {
        float v = rp[half*64 + j];
        ss += v*v;
    }
    ss += __shfl_xor_sync(0xffffffffu, ss, 1);
    const float inv = rsqrtf(ss * (1.0f/128.0f) + 1e-6f);

    const int token = mrow0 + row;
    const int s = token & (Sn-1);
    const float* cr = cosT + (size_t)s*Dn;
    const float* sr = sinT + (size_t)s*Dn;

    size_t base;
    if (mode == 0) base = ((size_t)token*Hn + hidx)*Dn;
    else           base = ((size_t)token*HKVn + hidx)*Dn;

    #pragma unroll 8
    for (int j = 0; j < 64; j += 2) {
        int d0 = half*64 + j;
        int d1 = d0 + 1;
        float nv0 = rp[d0]*inv*w[d0];
        float nv1 = rp[d1]*inv*w[d1];
        float ot0 = rp[d0^64]*inv*w[d0^64];
        float ot1 = rp[d1^64]*inv*w[d1^64];
        float rot0 = (d0 < 64) ? -ot0 : ot0;
        float rot1 = (d1 < 64) ? -ot1 : ot1;
        float r0 = nv0*cr[d0] + rot0*sr[d0];
        float r1 = nv1*cr[d1] + rot1*sr[d1];
        __half h0 = __float2half_rn(r0);
        __half h1 = __float2half_rn(r1);
        if (mode == 0) {
            *(uint32_t*)(qbh + base + d0) = packh(h0, h1);
            *(uint32_t*)(qbl + base + d0) =
                packh(__float2half_rn(r0 - __half2float(h0)),
                      __float2half_rn(r1 - __half2float(h1)));
        } else {
            *(uint32_t*)(kb + base + d0) = packh(h0, h1);
        }
    }
}

// ========== plain HMMA GEMM for O-projection (fp32 out) ===================
__global__ __launch_bounds__(256, 1)
void gemm_o(const __half* __restrict__ Ah, const __half* __restrict__ Al,
            const __half* __restrict__ Bw, float* __restrict__ C,
            int M, int N, int K)
{
    extern __shared__ __half smb[];
    const uint32_t sbase = smem_u32(smb);

    const int tid  = threadIdx.x;
    const int lane = tid & 31;
    const int wid  = tid >> 5;
    const int m0w  = (wid >> 2) * 64;
    const int n0w  = (wid & 3) * 32;
    const int mrow0 = blockIdx.y * 128;
    const int ncol0 = blockIdx.x * 128;
    const int NC = K / 32;

    float acc[4][4][4];
    #pragma unroll
    for (int mt = 0; mt < 4; mt++)
        #pragma unroll
        for (int nt = 0; nt < 4; nt++)
            #pragma unroll
            for (int i = 0; i < 4; i++) acc[mt][nt][i] = 0.f;

    auto load_chunk = [&](int c, int st) {
        const int k0 = c * 32;
        const uint32_t b0 = sbase + (uint32_t)st * HSTG;
        #pragma unroll
        for (int i = 0; i < 2; i++) {
            int id  = i*256 + tid;
            int row = id >> 2;
            int cc  = id & 3;
            uint32_t d  = (uint32_t)(row*80 + cc*16);
            size_t   ga = (size_t)(mrow0 + row)*K + k0 + cc*8;
            size_t   gb = (size_t)(ncol0 + row)*K + k0 + cc*8;
            cpasync16(b0 + 0*HARR*2 + d, Ah + ga);
            cpasync16(b0 + 1*HARR*2 + d, Al + ga);
            cpasync16(b0 + 2*HARR*2 + d, Bw + gb);
        }
        CP_COMMIT();
    };

    load_chunk(0, 0);
    load_chunk(1, 1);

    for (int c = 0; c < NC; c++) {
        if (c + 1 < NC) asm volatile("cp.async.wait_group 1;" ::: "memory");
        else            asm volatile("cp.async.wait_group 0;" ::: "memory");
        __syncthreads();
        if (c + 2 < NC) load_chunk(c + 2, (c + 2) % 3);

        const uint32_t b0  = sbase + (uint32_t)(c % 3) * HSTG;
        const uint32_t aHi = b0 + 0*HARR*2;
        const uint32_t aLo = b0 + 1*HARR*2;
        const uint32_t bB  = b0 + 2*HARR*2;

        #pragma unroll
        for (int ks = 0; ks < 2; ks++) {
            uint32_t ah[4][4], al[4][4], bf[2][4];
            const uint32_t aoff = (uint32_t)(ks*32 + (lane >> 4)*16);
            const uint32_t boff = (uint32_t)(ks*32 + ((lane >> 3) & 1)*16);
            #pragma unroll
            for (int mt = 0; mt < 4; mt++) {
                uint32_t r = (uint32_t)((m0w + mt*16 + (lane & 15)) * 80) + aoff;
                ldsm4(ah[mt], aHi + r);
                ldsm4(al[mt], aLo + r);
            }
            #pragma unroll
            for (int n2 = 0; n2 < 2; n2++) {
                uint32_t r = (uint32_t)((n0w + n2*16 + ((lane>>4)<<3) + (lane & 7)) * 80) + boff;
                ldsm4(bf[n2], bB + r);
            }
            #pragma unroll
            for (int mt = 0; mt < 4; mt++)
                #pragma unroll
                for (int nt = 0; nt < 4; nt++)
                    mma_f16(acc[mt][nt], ah[mt], &bf[nt>>1][(nt&1)*2]);
            #pragma unroll
            for (int mt = 0; mt < 4; mt++)
                #pragma unroll
                for (int nt = 0; nt < 4; nt++)
                    mma_f16(acc[mt][nt], al[mt], &bf[nt>>1][(nt&1)*2]);
        }
        __syncthreads();
    }

    #pragma unroll
    for (int mt = 0; mt < 4; mt++)
        #pragma unroll
        for (int nt = 0; nt < 4; nt++) {
            const float* d = acc[mt][nt];
            int row = mrow0 + m0w + mt*16 + (lane >> 2);
            int col = ncol0 + n0w + nt*8 + (lane & 3)*2;
            *(float2*)(C + (size_t)row*N + col)     = make_float2(d[0], d[1]);
            *(float2*)(C + (size_t)(row+8)*N + col) = make_float2(d[2], d[3]);
        }
}

// ============== causal flash attention (HMMA fp16, 2-term) ================
// grid (32 qtiles, 16 heads, 2 batch), 128 threads, BQ=64, BKV=64, D=128.
// FSMEM = 104448 -> 2 CTAs/SM.
#define FSTR 272                 // bytes per smem row (128 fp16 + 8 pad)
#define FQ_BYTES (64*FSTR)       // 17408
#define FKV_BYTES (64*FSTR)      // 17408
#define FSTAGE (2*FKV_BYTES)     // K, V = 34816
#define FSMEM (2*FQ_BYTES + 2*FSTAGE)  // 104448

__global__ __launch_bounds__(128, 2)
void flash_hmma(const __half* __restrict__ qh, const __half* __restrict__ qlp,
                const __half* __restrict__ kp, const __half* __restrict__ vp,
                __half* __restrict__ oh, __half* __restrict__ olp)
{
    extern __shared__ char smc[];
    const uint32_t sb = smem_u32(smc);
    const uint32_t Qh = sb, Ql = sb + FQ_BYTES;

    const int qt = gridDim.x - 1 - blockIdx.x;   // heavy tiles first
    const int h = blockIdx.y, b = blockIdx.z;
    const int kvh = h >> 2;
    const int tid = threadIdx.x, lane = tid & 31, w = tid >> 5;
    const float scale = 0.08838834764831845f;

    // Q tile (hi+lo): 64 rows x 16 chunks, hi AND lo per id -> 1024 ids
    #pragma unroll
    for (int i = 0; i < 8; i++) {
        int id = i*128 + tid;
        int row = id >> 4, ch = id & 15;
        size_t g = ((size_t)(b*Sn + qt*64 + row)*Hn + h)*Dn + ch*8;
        uint32_t d = (uint32_t)(row*FSTR + ch*16);
        cpasync16(Qh + d, qh  + g);
        cpasync16(Ql + d, qlp + g);
    }
    CP_COMMIT();

    auto load_kv = [&](int kt, int st) {
        uint32_t base = sb + 2*FQ_BYTES + (uint32_t)st * FSTAGE;
        #pragma unroll
        for (int i = 0; i < 8; i++) {
            int id = i*128 + tid;
            int row = id >> 4, ch = id & 15;
            size_t g = ((size_t)(b*Sn + kt*64 + row)*HKVn + kvh)*Dn + ch*8;
            uint32_t d = (uint32_t)(row*FSTR + ch*16);
            cpasync16(base + 0*FKV_BYTES + d, kp + g);
            cpasync16(base + 1*FKV_BYTES + d, vp + g);
        }
        CP_COMMIT();
    };

    const int nkv = qt + 1;
    load_kv(0, 0);

    float oacc[16][4];
    #pragma unroll
    for (int i = 0; i < 16; i++)
        #pragma unroll
        for (int j = 0; j < 4; j++) oacc[i][j] = 0.f;
    float m0 = -1e30f, m1 = -1e30f, l0 = 0.f, l1 = 0.f;
    const int gr0 = qt*64 + w*16 + (lane >> 2);
    const int gr1 = gr0 + 8;

    for (int kt = 0; kt < nkv; kt++) {
        asm volatile("cp.async.wait_group 0;" ::: "memory");
        __syncthreads();
        if (kt + 1 < nkv) load_kv(kt + 1, (kt + 1) & 1);

        const uint32_t kb2 = sb + 2*FQ_BYTES + (uint32_t)(kt & 1) * FSTAGE;

        // ---- S = Q K^T (Qh·K + Ql·K) ----
        float sacc[8][4];
        #pragma unroll
        for (int i = 0; i < 8; i++)
            #pragma unroll
            for (int j = 0; j < 4; j++) sacc[i][j] = 0.f;

        #pragma unroll
        for (int ks = 0; ks < 8; ks++) {
            uint32_t qhf[4], qlf[4], khf[4][4];
            const uint32_t aoff = (uint32_t)(ks*32 + (lane >> 4)*16);
            const uint32_t arow = (uint32_t)((w*16 + (lane & 15)) * FSTR);
            ldsm4(qhf, Qh + arow + aoff);
            ldsm4(qlf, Ql + arow + aoff);
            const uint32_t boff = (uint32_t)(ks*32 + ((lane >> 3) & 1)*16);
            #pragma unroll
            for (int n2 = 0; n2 < 4; n2++) {
                uint32_t r = (uint32_t)((n2*16 + ((lane>>4)<<3) + (lane & 7)) * FSTR) + boff;
                ldsm4(khf[n2], kb2 + r);
            }
            #pragma unroll
            for (int nt = 0; nt < 8; nt++)
                mma_f16(sacc[nt], qhf, &khf[nt>>1][(nt&1)*2]);
            #pragma unroll
            for (int nt = 0; nt < 8; nt++)
                mma_f16(sacc[nt], qlf, &khf[nt>>1][(nt&1)*2]);
        }

        // ---- softmax (online) ----
        const bool dz = (kt == qt);
        float mx0 = -1e30f, mx1 = -1e30f;
        #pragma unroll
        for (int nt = 0; nt < 8; nt++) {
            const int gc = kt*64 + nt*8 + (lane & 3)*2;
            float s0 = sacc[nt][0]*scale, s1 = sacc[nt][1]*scale;
            float s2 = sacc[nt][2]*scale, s3 = sacc[nt][3]*scale;
            if (dz) {
                if (gc     > gr0) s0 = -1e30f;
                if (gc + 1 > gr0) s1 = -1e30f;
                if (gc     > gr1) s2 = -1e30f;
                if (gc + 1 > gr1) s3 = -1e30f;
            }
            sacc[nt][0] = s0; sacc[nt][1] = s1; sacc[nt][2] = s2; sacc[nt][3] = s3;
            mx0 = fmaxf(mx0, fmaxf(s0, s1));
            mx1 = fmaxf(mx1, fmaxf(s2, s3));
        }
        mx0 = fmaxf(mx0, __shfl_xor_sync(0xffffffffu, mx0, 1));
        mx0 = fmaxf(mx0, __shfl_xor_sync(0xffffffffu, mx0, 2));
        mx1 = fmaxf(mx1, __shfl_xor_sync(0xffffffffu, mx1, 1));
        mx1 = fmaxf(mx1, __shfl_xor_sync(0xffffffffu, mx1, 2));
        const float mn0 = fmaxf(m0, mx0), mn1 = fmaxf(m1, mx1);
        const float cr0 = __expf(m0 - mn0), cr1 = __expf(m1 - mn1);
        m0 = mn0; m1 = mn1;

        uint32_t pha[8], phb[8], pla[8], plb[8];
        float sum0 = 0.f, sum1 = 0.f;
        #pragma unroll
        for (int nt = 0; nt < 8; nt++) {
            float p0 = __expf(sacc[nt][0] - mn0);
            float p1 = __expf(sacc[nt][1] - mn0);
            float p2 = __expf(sacc[nt][2] - mn1);
            float p3 = __expf(sacc[nt][3] - mn1);
            sum0 += p0 + p1; sum1 += p2 + p3;
            __half h0 = __float2half_rn(p0);
            __half h1 = __float2half_rn(p1);
            __half h2 = __float2half_rn(p2);
            __half h3 = __float2half_rn(p3);
            pha[nt] = packh(h0, h1);
            phb[nt] = packh(h2, h3);
            pla[nt] = packh(__float2half_rn(p0 - __half2float(h0)),
                            __float2half_rn(p1 - __half2float(h1)));
            plb[nt] = packh(__float2half_rn(p2 - __half2float(h2)),
                            __float2half_rn(p3 - __half2float(h3)));
        }
        sum0 += __shfl_xor_sync(0xffffffffu, sum0, 1);
        sum0 += __shfl_xor_sync(0xffffffffu, sum0, 2);
        sum1 += __shfl_xor_sync(0xffffffffu, sum1, 1);
        sum1 += __shfl_xor_sync(0xffffffffu, sum1, 2);
        l0 = l0*cr0 + sum0;
        l1 = l1*cr1 + sum1;
        #pragma unroll
        for (int nt = 0; nt < 16; nt++) {
            oacc[nt][0] *= cr0; oacc[nt][1] *= cr0;
            oacc[nt][2] *= cr1; oacc[nt][3] *= cr1;
        }

        // ---- O += P V (Ph·V + Pl·V), V via ldmatrix.trans ----
        #pragma unroll
        for (int ks = 0; ks < 4; ks++) {
            uint32_t ah4[4] = { pha[2*ks], phb[2*ks], pha[2*ks+1], phb[2*ks+1] };
            uint32_t al4[4] = { pla[2*ks], plb[2*ks], pla[2*ks+1], plb[2*ks+1] };
            const uint32_t vrow = (uint32_t)((ks*16 + ((lane>>3)&1)*8 + (lane&7)) * FSTR);
            #pragma unroll
            for (int half = 0; half < 2; half++) {
                uint32_t vhf[4][4];
                #pragma unroll
                for (int n2 = 0; n2 < 4; n2++) {
                    uint32_t coff = (uint32_t)(((half*4 + n2)*2 + (lane>>4)) * 16);
                    ldsm4t(vhf[n2], kb2 + 1*FKV_BYTES + vrow + coff);
                }
                #pragma unroll
                for (int nt = 0; nt < 8; nt++)
                    mma_f16(oacc[half*8 + nt], ah4, &vhf[nt>>1][(nt&1)*2]);
                #pragma unroll
                for (int nt = 0; nt < 8; nt++)
                    mma_f16(oacc[half*8 + nt], al4, &vhf[nt>>1][(nt&1)*2]);
            }
        }
    }

    // epilogue: normalize and emit hi/lo fp16
    const float inv0 = 1.f / l0, inv1 = 1.f / l1;
    const size_t t0 = (size_t)(b*Sn + qt*64 + w*16 + (lane >> 2));
    const size_t r0base = (t0*Hn + h)*Dn;
    const size_t r1base = ((t0 + 8)*Hn + h)*Dn;
    #pragma unroll
    for (int nt = 0; nt < 16; nt++) {
        const int col = nt*8 + (lane & 3)*2;
        float o0 = oacc[nt][0]*inv0, o1 = oacc[nt][1]*inv0;
        float o2 = oacc[nt][2]*inv1, o3 = oacc[nt][3]*inv1;
        __half h0 = __float2half_rn(o0), h1 = __float2half_rn(o1);
        __half h2 = __float2half_rn(o2), h3 = __float2half_rn(o3);
        *(uint32_t*)(oh  + r0base + col) = packh(h0, h1);
        *(uint32_t*)(oh  + r1base + col) = packh(h2, h3);
        *(uint32_t*)(olp + r0base + col) =
            packh(__float2half_rn(o0 - __half2float(h0)),
                  __float2half_rn(o1 - __half2float(h1)));
        *(uint32_t*)(olp + r1base + col) =
            packh(__float2half_rn(o2 - __half2float(h2)),
                  __float2half_rn(o3 - __half2float(h3)));
    }
}

// ==================== launch =============================================
extern "C" void kernel_launch(void* const* d_in, const int* in_sizes, int n_in,
                              void* d_out, int out_size)
{
    const float* x    = (const float*)d_in[0];
    const float* cosT = (const float*)d_in[1];
    const float* sinT = (const float*)d_in[2];
    // d_in[3] = mask (exact causal -1e9 triu) -> applied analytically
    const float* wq   = (const float*)d_in[4];
    const float* wk   = (const float*)d_in[5];
    const float* wv   = (const float*)d_in[6];
    const float* wo   = (const float*)d_in[7];
    const float* qw   = (const float*)d_in[8];
    const float* kw   = (const float*)d_in[9];
    float* out = (float*)d_out;

    __half *xh, *xl, *wqp, *wkp, *wvp, *wop;
    __half *qbh, *qbl, *kb, *vb, *aoh, *aol;
    cudaGetSymbolAddress((void**)&xh,  g_xh);  cudaGetSymbolAddress((void**)&xl, g_xl);
    cudaGetSymbolAddress((void**)&wqp, g_wq);
    cudaGetSymbolAddress((void**)&wkp, g_wk);
    cudaGetSymbolAddress((void**)&wvp, g_wv);
    cudaGetSymbolAddress((void**)&wop, g_wo);
    cudaGetSymbolAddress((void**)&qbh, g_qbh); cudaGetSymbolAddress((void**)&qbl, g_qbl);
    cudaGetSymbolAddress((void**)&kb,  g_kb);
    cudaGetSymbolAddress((void**)&vb,  g_vb);
    cudaGetSymbolAddress((void**)&aoh, g_aoh); cudaGetSymbolAddress((void**)&aol, g_aol);

    // conversions
    {
        int nx4 = (int)(((size_t)Tn*HSn)/4);
        cvt_hilo_h<<<(nx4+255)/256, 256>>>(x, xh, xl, nx4);
        int nq = (int)(((size_t)Hn*Dn*HSn)/4);
        int nk = (int)(((size_t)HKVn*Dn*HSn)/4);
        int no = (int)(((size_t)HSn*Hn*Dn)/4);
        int ntot = nq + nk + nk + no;
        cvt_w4<<<(ntot+255)/256, 256>>>(wq, wqp, nq, wk, wkp, nk,
                                        wv, wvp, nk, wo, wop, no);
    }

    // fused QKV projection + norm + rope + fp16 emit (one launch)
    cudaFuncSetAttribute(gemm_qkv, cudaFuncAttributeMaxDynamicSharedMemorySize, HSMEM);
    gemm_qkv<<<dim3(24, Tn/128), 256, HSMEM>>>(
        xh, xl, wqp, wkp, wvp, cosT, sinT, qw, kw, qbh, qbl, kb, vb);

    // causal flash attention (fp16 2-term, BQ=64, 2 CTAs/SM)
    cudaFuncSetAttribute(flash_hmma, cudaFuncAttributeMaxDynamicSharedMemorySize, FSMEM);
    flash_hmma<<<dim3(Sn/64, Hn, Bn), 128, FSMEM>>>(qbh, qbl, kb, vb, aoh, aol);

    // output projection
    cudaFuncSetAttribute(gemm_o, cudaFuncAttributeMaxDynamicSharedMemorySize, HSMEM);
    gemm_o<<<dim3(HSn/128, Tn/128), 256, HSMEM>>>(
        aoh, aol, wop, out, Tn, HSn, Hn*Dn);
}